// round 2
// baseline (speedup 1.0000x reference)
#include <cuda_runtime.h>
#include <math_constants.h>

#define Bn   4
#define Sn   4096
#define DIMn 1024
#define RANKn 32
#define BSn  (Bn * Sn)

// ---------------- scratch (__device__ globals, no allocation) ----------------
__device__ float g_xq[(size_t)BSn * RANKn];          // 2 MB   (pre-scaled by 1/sqrt(D))
__device__ float g_xk[(size_t)BSn * RANKn];          // 2 MB
__device__ float g_y [(size_t)BSn * DIMn];           // 64 MB  y = x @ VO
__device__ float g_P [(size_t)Bn * Sn * Sn];         // 256 MB scores -> exp(scores - m)
__device__ float g_m   [BSn];                        // row max
__device__ float g_sinv[BSn];                        // 1 / row sum

// ---------------- K1: low-rank projections ----------------
// grid = BS, block = 64. Thread t<32 -> Q row t, t>=32 -> K row t-32.
__global__ void proj_kernel(const float* __restrict__ x,
                            const float* __restrict__ Qw,
                            const float* __restrict__ Kw) {
    __shared__ float xs[DIMn];
    const int row = blockIdx.x;
    const float4* xr = (const float4*)(x + (size_t)row * DIMn);
    float4* xs4w = (float4*)xs;
    for (int i = threadIdx.x; i < DIMn / 4; i += 64) xs4w[i] = xr[i];
    __syncthreads();

    const int t = threadIdx.x;
    const float* W = (t < RANKn ? Qw : Kw) + (size_t)(t & (RANKn - 1)) * DIMn;
    const float4* W4  = (const float4*)W;
    const float4* xs4 = (const float4*)xs;
    float a0 = 0.f, a1 = 0.f, a2 = 0.f, a3 = 0.f;
#pragma unroll 4
    for (int d = 0; d < DIMn / 4; d++) {
        float4 w = W4[d], v = xs4[d];
        a0 += w.x * v.x; a1 += w.y * v.y; a2 += w.z * v.z; a3 += w.w * v.w;
    }
    float acc = (a0 + a1) + (a2 + a3);
    if (t < RANKn) g_xq[(size_t)row * RANKn + t]           = acc * 0.03125f; // 1/sqrt(1024)
    else           g_xk[(size_t)row * RANKn + (t - RANKn)] = acc;
}

// ---------------- K3: raw scores + row max ----------------
// grid = BS/128 blocks, 128 threads. Thread owns one query row.
__global__ void scores_kernel() {
    constexpr int QT = 128;
    constexpr int KT = 32;
    const int tilesPerBatch = Sn / QT;
    const int b  = blockIdx.x / tilesPerBatch;
    const int qt = blockIdx.x % tilesPerBatch;
    const int row = threadIdx.x;            // 0..127
    const size_t qbase = (size_t)b * Sn + (size_t)qt * QT;

    // preload this thread's xq row into registers
    float xqr[RANKn];
    {
        const float4* p = (const float4*)(g_xq + (qbase + row) * RANKn);
#pragma unroll
        for (int i = 0; i < RANKn / 4; i++) {
            float4 v = p[i];
            xqr[i * 4 + 0] = v.x; xqr[i * 4 + 1] = v.y;
            xqr[i * 4 + 2] = v.z; xqr[i * 4 + 3] = v.w;
        }
    }

    __shared__ float xk_s[KT][RANKn];       // 4 KB
    __shared__ float sc_s[QT][KT + 1];      // ~16.9 KB (padded vs bank conflicts)

    float m = -1e30f;
    const int w    = threadIdx.x >> 5;
    const int lane = threadIdx.x & 31;

    for (int u0 = 0; u0 < Sn; u0 += KT) {
        // load key tile
        {
            const float4* src = (const float4*)(g_xk + ((size_t)b * Sn + u0) * RANKn);
            float4* dst = (float4*)&xk_s[0][0];
            for (int i = threadIdx.x; i < KT * RANKn / 4; i += 128) dst[i] = src[i];
        }
        __syncthreads();
#pragma unroll 2
        for (int u = 0; u < KT; u++) {
            const float* kr = xk_s[u];
            float a0 = 0.f, a1 = 0.f, a2 = 0.f, a3 = 0.f;
#pragma unroll
            for (int r = 0; r < RANKn; r += 4) {
                a0 += xqr[r + 0] * kr[r + 0];
                a1 += xqr[r + 1] * kr[r + 1];
                a2 += xqr[r + 2] * kr[r + 2];
                a3 += xqr[r + 3] * kr[r + 3];
            }
            float sc = (a0 + a1) + (a2 + a3);
            sc_s[row][u] = sc;
            m = fmaxf(m, sc);
        }
        __syncthreads();
        // coalesced write: warp w writes rows [w*32, w*32+32), lane = key column
#pragma unroll 4
        for (int rr = 0; rr < 32; rr++) {
            int r = w * 32 + rr;
            g_P[(qbase + r) * Sn + u0 + lane] = sc_s[r][lane];
        }
        __syncthreads();  // protect sc_s / xk_s before next iteration overwrites
    }
    g_m[qbase + row] = m;
}

// ---------------- K4: P = exp(raw - m), sinv = 1/rowsum ----------------
// grid = BS, block = 256
__global__ void expsum_kernel() {
    const size_t row = blockIdx.x;
    const float m = g_m[row];
    float4* prow = (float4*)(g_P + row * (size_t)Sn);
    float sum = 0.f;
    for (int i = threadIdx.x; i < Sn / 4; i += 256) {
        float4 v = prow[i];
        v.x = __expf(v.x - m); v.y = __expf(v.y - m);
        v.z = __expf(v.z - m); v.w = __expf(v.w - m);
        sum += (v.x + v.y) + (v.z + v.w);
        prow[i] = v;
    }
    __shared__ float red[256];
    red[threadIdx.x] = sum;
    __syncthreads();
    for (int s2 = 128; s2 > 0; s2 >>= 1) {
        if (threadIdx.x < s2) red[threadIdx.x] += red[threadIdx.x + s2];
        __syncthreads();
    }
    if (threadIdx.x == 0) g_sinv[row] = 1.0f / red[0];
}

// ---------------- SGEMM: C = A(MxK) * B(KxN), row-major, batched ----------------
// optional per-output-row scale (sinv) applied in epilogue
__global__ void __launch_bounds__(256, 2)
sgemm_kernel(const float* __restrict__ A, const float* __restrict__ Bm,
             float* __restrict__ C, const float* __restrict__ sinv,
             int M, int N, int Kd,
             size_t sA, size_t sB, size_t sC, size_t sSinv) {
    constexpr int BM = 128, BN = 128, BK = 8, TM = 8, TN = 8;
    A  += (size_t)blockIdx.z * sA;
    Bm += (size_t)blockIdx.z * sB;
    C  += (size_t)blockIdx.z * sC;
    const float* sv = sinv ? sinv + (size_t)blockIdx.z * sSinv : nullptr;

    __shared__ float As[BK][BM + 4];
    __shared__ float Bs[BK][BN];

    const int tid  = threadIdx.x;
    const int tcol = tid & 15;     // 0..15
    const int trow = tid >> 4;     // 0..15
    const int cRow = blockIdx.y * BM;
    const int cCol = blockIdx.x * BN;

    const int aRow = tid >> 1;            // 0..127
    const int aCol = (tid & 1) * 4;       // 0 or 4
    const int bRow = tid >> 5;            // 0..7
    const int bCol = (tid & 31) * 4;

    const float* Aptr = A + (size_t)(cRow + aRow) * Kd + aCol;
    const float* Bptr = Bm + (size_t)bRow * N + cCol + bCol;

    float acc[TM][TN] = {};

    for (int k0 = 0; k0 < Kd; k0 += BK) {
        float4 av = *(const float4*)Aptr;
        float4 bv = *(const float4*)Bptr;
        Aptr += BK;
        Bptr += (size_t)BK * N;
        As[aCol + 0][aRow] = av.x;
        As[aCol + 1][aRow] = av.y;
        As[aCol + 2][aRow] = av.z;
        As[aCol + 3][aRow] = av.w;
        *(float4*)&Bs[bRow][bCol] = bv;
        __syncthreads();
#pragma unroll
        for (int k = 0; k < BK; k++) {
            float ar[TM], br[TN];
#pragma unroll
            for (int i = 0; i < TM; i++) ar[i] = As[k][trow * TM + i];
#pragma unroll
            for (int j = 0; j < TN; j++) br[j] = Bs[k][tcol * TN + j];
#pragma unroll
            for (int i = 0; i < TM; i++)
#pragma unroll
                for (int j = 0; j < TN; j++) acc[i][j] += ar[i] * br[j];
        }
        __syncthreads();
    }

#pragma unroll
    for (int i = 0; i < TM; i++) {
        const int r = cRow + trow * TM + i;
        const float scale = sv ? sv[r] : 1.0f;
        float4 c0 = make_float4(acc[i][0] * scale, acc[i][1] * scale,
                                acc[i][2] * scale, acc[i][3] * scale);
        float4 c1 = make_float4(acc[i][4] * scale, acc[i][5] * scale,
                                acc[i][6] * scale, acc[i][7] * scale);
        float4* cp = (float4*)(C + (size_t)r * N + cCol + tcol * TN);
        cp[0] = c0;
        cp[1] = c1;
    }
}

// ---------------- launch ----------------
extern "C" void kernel_launch(void* const* d_in, const int* in_sizes, int n_in,
                              void* d_out, int out_size) {
    const float* x  = (const float*)d_in[0];
    const float* Qw = (const float*)d_in[1];
    const float* Kw = (const float*)d_in[2];
    const float* VO = (const float*)d_in[3];
    float* out = (float*)d_out;

    float *pY, *pP, *pSinv;
    cudaGetSymbolAddress((void**)&pY, g_y);
    cudaGetSymbolAddress((void**)&pP, g_P);
    cudaGetSymbolAddress((void**)&pSinv, g_sinv);

    // K1: projections (xq scaled by 1/sqrt(D))
    proj_kernel<<<BSn, 64>>>(x, Qw, Kw);

    // K2: y = x @ VO  (M=BS, K=D, N=D)
    {
        dim3 grid(DIMn / 128, BSn / 128, 1);
        sgemm_kernel<<<grid, 256>>>(x, VO, pY, nullptr,
                                    BSn, DIMn, DIMn, 0, 0, 0, 0);
    }

    // K3: raw scores + row max
    scores_kernel<<<BSn / 128, 128>>>();

    // K4: exponentiate + row-sum reciprocal
    expsum_kernel<<<BSn, 256>>>();

    // K5: out = diag(sinv) * (P @ y), batched over B  (M=S, K=S, N=D)
    {
        dim3 grid(DIMn / 128, Sn / 128, Bn);
        sgemm_kernel<<<grid, 256>>>(pP, pY, out, pSinv,
                                    Sn, DIMn, Sn,
                                    (size_t)Sn * Sn, (size_t)Sn * DIMn,
                                    (size_t)Sn * DIMn, (size_t)Sn);
    }
}

// round 3
// speedup vs baseline: 1.0014x; 1.0014x over previous
#include <cuda_runtime.h>
#include <math_constants.h>

#define Bn   4
#define Sn   4096
#define DIMn 1024
#define RANKn 32
#define BSn  (Bn * Sn)

// ---------------- scratch (__device__ globals, no allocation) ----------------
__device__ float g_xq[(size_t)BSn * RANKn];          // 2 MB   (pre-scaled by 1/sqrt(D))
__device__ float g_xk[(size_t)BSn * RANKn];          // 2 MB
__device__ float g_y [(size_t)BSn * DIMn];           // 64 MB  y = x @ VO
__device__ float g_P [(size_t)Bn * Sn * Sn];         // 256 MB scores -> exp(scores - m)
__device__ float g_m   [BSn];                        // row max
__device__ float g_sinv[BSn];                        // 1 / row sum

// ---------------- K1: low-rank projections ----------------
// grid = BS, block = 64. Thread t<32 -> Q row t, t>=32 -> K row t-32.
__global__ void proj_kernel(const float* __restrict__ x,
                            const float* __restrict__ Qw,
                            const float* __restrict__ Kw) {
    __shared__ float xs[DIMn];
    const int row = blockIdx.x;
    const float4* xr = (const float4*)(x + (size_t)row * DIMn);
    float4* xs4w = (float4*)xs;
    for (int i = threadIdx.x; i < DIMn / 4; i += 64) xs4w[i] = xr[i];
    __syncthreads();

    const int t = threadIdx.x;
    const float* W = (t < RANKn ? Qw : Kw) + (size_t)(t & (RANKn - 1)) * DIMn;
    const float4* W4  = (const float4*)W;
    const float4* xs4 = (const float4*)xs;
    float a0 = 0.f, a1 = 0.f, a2 = 0.f, a3 = 0.f;
#pragma unroll 4
    for (int d = 0; d < DIMn / 4; d++) {
        float4 w = W4[d], v = xs4[d];
        a0 += w.x * v.x; a1 += w.y * v.y; a2 += w.z * v.z; a3 += w.w * v.w;
    }
    float acc = (a0 + a1) + (a2 + a3);
    if (t < RANKn) g_xq[(size_t)row * RANKn + t]           = acc * 0.03125f; // 1/sqrt(1024)
    else           g_xk[(size_t)row * RANKn + (t - RANKn)] = acc;
}

// ---------------- K3: raw scores + row max ----------------
// grid = BS/128 blocks, 128 threads. Thread owns one query row.
__global__ void scores_kernel() {
    constexpr int QT = 128;
    constexpr int KT = 32;
    const int tilesPerBatch = Sn / QT;
    const int b  = blockIdx.x / tilesPerBatch;
    const int qt = blockIdx.x % tilesPerBatch;
    const int row = threadIdx.x;            // 0..127
    const size_t qbase = (size_t)b * Sn + (size_t)qt * QT;

    // preload this thread's xq row into registers
    float xqr[RANKn];
    {
        const float4* p = (const float4*)(g_xq + (qbase + row) * RANKn);
#pragma unroll
        for (int i = 0; i < RANKn / 4; i++) {
            float4 v = p[i];
            xqr[i * 4 + 0] = v.x; xqr[i * 4 + 1] = v.y;
            xqr[i * 4 + 2] = v.z; xqr[i * 4 + 3] = v.w;
        }
    }

    __shared__ float xk_s[KT][RANKn];       // 4 KB
    __shared__ float sc_s[QT][KT + 1];      // ~16.9 KB (padded vs bank conflicts)

    float m = -1e30f;
    const int w    = threadIdx.x >> 5;
    const int lane = threadIdx.x & 31;

    for (int u0 = 0; u0 < Sn; u0 += KT) {
        // load key tile
        {
            const float4* src = (const float4*)(g_xk + ((size_t)b * Sn + u0) * RANKn);
            float4* dst = (float4*)&xk_s[0][0];
            for (int i = threadIdx.x; i < KT * RANKn / 4; i += 128) dst[i] = src[i];
        }
        __syncthreads();
#pragma unroll 2
        for (int u = 0; u < KT; u++) {
            const float* kr = xk_s[u];
            float a0 = 0.f, a1 = 0.f, a2 = 0.f, a3 = 0.f;
#pragma unroll
            for (int r = 0; r < RANKn; r += 4) {
                a0 += xqr[r + 0] * kr[r + 0];
                a1 += xqr[r + 1] * kr[r + 1];
                a2 += xqr[r + 2] * kr[r + 2];
                a3 += xqr[r + 3] * kr[r + 3];
            }
            float sc = (a0 + a1) + (a2 + a3);
            sc_s[row][u] = sc;
            m = fmaxf(m, sc);
        }
        __syncthreads();
        // coalesced write: warp w writes rows [w*32, w*32+32), lane = key column
#pragma unroll 4
        for (int rr = 0; rr < 32; rr++) {
            int r = w * 32 + rr;
            g_P[(qbase + r) * Sn + u0 + lane] = sc_s[r][lane];
        }
        __syncthreads();  // protect sc_s / xk_s before next iteration overwrites
    }
    g_m[qbase + row] = m;
}

// ---------------- K4: P = exp(raw - m), sinv = 1/rowsum ----------------
// grid = BS, block = 256
__global__ void expsum_kernel() {
    const size_t row = blockIdx.x;
    const float m = g_m[row];
    float4* prow = (float4*)(g_P + row * (size_t)Sn);
    float sum = 0.f;
    for (int i = threadIdx.x; i < Sn / 4; i += 256) {
        float4 v = prow[i];
        v.x = __expf(v.x - m); v.y = __expf(v.y - m);
        v.z = __expf(v.z - m); v.w = __expf(v.w - m);
        sum += (v.x + v.y) + (v.z + v.w);
        prow[i] = v;
    }
    __shared__ float red[256];
    red[threadIdx.x] = sum;
    __syncthreads();
    for (int s2 = 128; s2 > 0; s2 >>= 1) {
        if (threadIdx.x < s2) red[threadIdx.x] += red[threadIdx.x + s2];
        __syncthreads();
    }
    if (threadIdx.x == 0) g_sinv[row] = 1.0f / red[0];
}

// ---------------- SGEMM: C = A(MxK) * B(KxN), row-major, batched ----------------
// optional per-output-row scale (sinv) applied in epilogue
__global__ void __launch_bounds__(256, 2)
sgemm_kernel(const float* __restrict__ A, const float* __restrict__ Bm,
             float* __restrict__ C, const float* __restrict__ sinv,
             int M, int N, int Kd,
             size_t sA, size_t sB, size_t sC, size_t sSinv) {
    constexpr int BM = 128, BN = 128, BK = 8, TM = 8, TN = 8;
    A  += (size_t)blockIdx.z * sA;
    Bm += (size_t)blockIdx.z * sB;
    C  += (size_t)blockIdx.z * sC;
    const float* sv = sinv ? sinv + (size_t)blockIdx.z * sSinv : nullptr;

    __shared__ float As[BK][BM + 4];
    __shared__ float Bs[BK][BN];

    const int tid  = threadIdx.x;
    const int tcol = tid & 15;     // 0..15
    const int trow = tid >> 4;     // 0..15
    const int cRow = blockIdx.y * BM;
    const int cCol = blockIdx.x * BN;

    const int aRow = tid >> 1;            // 0..127
    const int aCol = (tid & 1) * 4;       // 0 or 4
    const int bRow = tid >> 5;            // 0..7
    const int bCol = (tid & 31) * 4;

    const float* Aptr = A + (size_t)(cRow + aRow) * Kd + aCol;
    const float* Bptr = Bm + (size_t)bRow * N + cCol + bCol;

    float acc[TM][TN] = {};

    for (int k0 = 0; k0 < Kd; k0 += BK) {
        float4 av = *(const float4*)Aptr;
        float4 bv = *(const float4*)Bptr;
        Aptr += BK;
        Bptr += (size_t)BK * N;
        As[aCol + 0][aRow] = av.x;
        As[aCol + 1][aRow] = av.y;
        As[aCol + 2][aRow] = av.z;
        As[aCol + 3][aRow] = av.w;
        *(float4*)&Bs[bRow][bCol] = bv;
        __syncthreads();
#pragma unroll
        for (int k = 0; k < BK; k++) {
            float ar[TM], br[TN];
#pragma unroll
            for (int i = 0; i < TM; i++) ar[i] = As[k][trow * TM + i];
#pragma unroll
            for (int j = 0; j < TN; j++) br[j] = Bs[k][tcol * TN + j];
#pragma unroll
            for (int i = 0; i < TM; i++)
#pragma unroll
                for (int j = 0; j < TN; j++) acc[i][j] += ar[i] * br[j];
        }
        __syncthreads();
    }

#pragma unroll
    for (int i = 0; i < TM; i++) {
        const int r = cRow + trow * TM + i;
        const float scale = sv ? sv[r] : 1.0f;
        float4 c0 = make_float4(acc[i][0] * scale, acc[i][1] * scale,
                                acc[i][2] * scale, acc[i][3] * scale);
        float4 c1 = make_float4(acc[i][4] * scale, acc[i][5] * scale,
                                acc[i][6] * scale, acc[i][7] * scale);
        float4* cp = (float4*)(C + (size_t)r * N + cCol + tcol * TN);
        cp[0] = c0;
        cp[1] = c1;
    }
}

// ---------------- launch ----------------
extern "C" void kernel_launch(void* const* d_in, const int* in_sizes, int n_in,
                              void* d_out, int out_size) {
    const float* x  = (const float*)d_in[0];
    const float* Qw = (const float*)d_in[1];
    const float* Kw = (const float*)d_in[2];
    const float* VO = (const float*)d_in[3];
    float* out = (float*)d_out;

    float *pY, *pP, *pSinv;
    cudaGetSymbolAddress((void**)&pY, g_y);
    cudaGetSymbolAddress((void**)&pP, g_P);
    cudaGetSymbolAddress((void**)&pSinv, g_sinv);

    // K1: projections (xq scaled by 1/sqrt(D))
    proj_kernel<<<BSn, 64>>>(x, Qw, Kw);

    // K2: y = x @ VO  (M=BS, K=D, N=D)
    {
        dim3 grid(DIMn / 128, BSn / 128, 1);
        sgemm_kernel<<<grid, 256>>>(x, VO, pY, nullptr,
                                    BSn, DIMn, DIMn, 0, 0, 0, 0);
    }

    // K3: raw scores + row max
    scores_kernel<<<BSn / 128, 128>>>();

    // K4: exponentiate + row-sum reciprocal
    expsum_kernel<<<BSn, 256>>>();

    // K5: out = diag(sinv) * (P @ y), batched over B  (M=S, K=S, N=D)
    {
        dim3 grid(DIMn / 128, Sn / 128, Bn);
        sgemm_kernel<<<grid, 256>>>(pP, pY, out, pSinv,
                                    Sn, DIMn, Sn,
                                    (size_t)Sn * Sn, (size_t)Sn * DIMn,
                                    (size_t)Sn * DIMn, (size_t)Sn);
    }
}